// round 15
// baseline (speedup 1.0000x reference)
#include <cuda_runtime.h>
#include <math.h>

#define H_DIM 1024
#define NAG 256
#define BTOK 8192
#define NTH 256
#define SB 48
#define TPW 6
#define NPROD 40
#define GRID_MAIN 296
#define LN_EPS 1e-5f
#define ALPHA_MAX 5.0f

typedef unsigned long long u64;

// ---- global scratch ----
__device__ int g_cnt[NAG];          // zeroed by builder each run
__device__ int g_cnt2[NAG];
__device__ int g_toks[NAG][BTOK];
__device__ int g_items[512];        // overflow items only (batch >= 1)
__device__ int g_nitems;
__device__ int g_ifetch;
__device__ int g_sdone;             // producer scatter done-count
__device__ volatile int g_bdone;    // build complete flag
__device__ int g_fin;               // finish count for reset

// ---- f32x2 packed math ----
__device__ __forceinline__ u64 fma2(u64 a, u64 b, u64 c) {
    u64 d;
    asm("fma.rn.f32x2 %0, %1, %2, %3;" : "=l"(d) : "l"(a), "l"(b), "l"(c));
    return d;
}
__device__ __forceinline__ u64 add2(u64 a, u64 b) {
    u64 d;
    asm("add.rn.f32x2 %0, %1, %2;" : "=l"(d) : "l"(a), "l"(b));
    return d;
}
__device__ __forceinline__ u64 mul2(u64 a, u64 b) {
    u64 d;
    asm("mul.rn.f32x2 %0, %1, %2;" : "=l"(d) : "l"(a), "l"(b));
    return d;
}
__device__ __forceinline__ u64 pack2(float lo, float hi) {
    u64 d;
    asm("mov.b64 %0, {%1, %2};" : "=l"(d) : "f"(lo), "f"(hi));
    return d;
}
__device__ __forceinline__ void unpack2(u64 v, float& lo, float& hi) {
    asm("mov.b64 {%0, %1}, %2;" : "=f"(lo), "=f"(hi) : "l"(v));
}

// ---- cp.async helpers ----
__device__ __forceinline__ void cp16(void* s, const void* g) {
    unsigned sa = (unsigned)__cvta_generic_to_shared(s);
    asm volatile("cp.async.cg.shared.global [%0], [%1], 16;\n" :: "r"(sa), "l"(g));
}
#define CP_COMMIT() asm volatile("cp.async.commit_group;\n" ::: "memory")
#define CP_WAIT2()  asm volatile("cp.async.wait_group 2;\n" ::: "memory")
#define CP_WAIT1()  asm volatile("cp.async.wait_group 1;\n" ::: "memory")
#define CP_WAIT0()  asm volatile("cp.async.wait_group 0;\n" ::: "memory")

// SMEM layout (floats): ring 4 x 5120 @0 (80KB), binter @20480 (12KB), stoks @23552
#define STAGE_F 5120
#define OFF_BI 20480
#define OFF_TK 23552
#define SMEM_BYTES ((23552 + 48) * 4)

// A-chunk t in [0,16): U 64k x 32r (2048 f) + h 48tok x 64k (3072 f). t in [16,24): V 32r x 128j.
__device__ __forceinline__ void issue_A_U(int t, float* smem, const float4* pu4, int tid) {
    float4* dst = (float4*)(smem + (t & 3) * STAGE_F);
    cp16(dst + tid,       pu4 + t * 512 + tid);
    cp16(dst + 256 + tid, pu4 + t * 512 + 256 + tid);
}
__device__ __forceinline__ void issue_A_H(int t, float* smem, const float4* h4,
                                          const int* stoks, int tid) {
    float4* dst = (float4*)(smem + (t & 3) * STAGE_F);
    #pragma unroll
    for (int i = 0; i < 3; ++i) {
        const int idx = tid + i * 256;
        const int tok = idx >> 4, cc = idx & 15;
        cp16(dst + 512 + idx, h4 + (size_t)stoks[tok] * 256 + t * 16 + cc);
    }
}
__device__ __forceinline__ void issue_chunk(int t, float* smem, const float4* pu4,
                                            const float4* pv4, const float4* h4,
                                            const int* stoks, int tid) {
    if (t < 16) {
        issue_A_U(t, smem, pu4, tid);
        issue_A_H(t, smem, h4, stoks, tid);
    } else {
        const int j = t - 16;
        float4* dst = (float4*)(smem + (t & 3) * STAGE_F);
        #pragma unroll
        for (int i = 0; i < 4; ++i) {
            const int idx = tid + i * 256;
            const int r = idx >> 5, cc = idx & 31;
            cp16(dst + idx, pv4 + r * 256 + j * 32 + cc);
        }
    }
}

__global__ __launch_bounds__(NTH, 2)
void div_inject_kernel(const float* __restrict__ h,
                       const float* __restrict__ log_alpha,
                       const float* __restrict__ gamma,
                       const float* __restrict__ beta,
                       const float* __restrict__ pu,
                       const float* __restrict__ pv,
                       const int*   __restrict__ ids,
                       float*       __restrict__ out)
{
    extern __shared__ float smem[];
    u64* bint  = (u64*)(smem + OFF_BI);
    int* stoks = (int*)(smem + OFF_TK);
    __shared__ int s_item;
    __shared__ int s_last;

    const int tid  = threadIdx.x;
    const int lane = tid & 31;
    const int wid  = tid >> 5;
    const int cta  = blockIdx.x;

    const float alpha = fminf(expf(log_alpha[0]), ALPHA_MAX);
    const u64 al2 = pack2(alpha, alpha);
    const float4* h4 = (const float4*)h;
    const ulonglong2* h2 = (const ulonglong2*)h;
    ulonglong2* out2 = (ulonglong2*)out;

    int next_static = -1;

    if (cta < NPROD) {
        // ============ producer: scatter ids, last builds items ============
        const int i = cta * NTH + tid;
        if (i < BTOK) {
            int a = ids[i] & (NAG - 1);
            int p = atomicAdd(&g_cnt[a], 1);
            g_toks[a][p] = i;
        }
        __threadfence();
        __syncthreads();
        if (tid == 0) s_last = (atomicAdd(&g_sdone, 1) == NPROD - 1) ? 1 : 0;
        __syncthreads();
        if (s_last) {
            if (tid == 0) { g_nitems = 0; g_ifetch = 0; }
            __syncthreads();
            __threadfence();
            const int a = tid;              // 256 threads = 256 agents
            const int n = g_cnt[a];
            g_cnt[a] = 0;
            g_cnt2[a] = n;
            for (int b = 1; b * SB < n; ++b) {
                int p = atomicAdd(&g_nitems, 1);
                g_items[p] = a | (b << 8);
            }
            __syncthreads();
            __threadfence();
            if (tid == 0) g_bdone = 1;
        } else {
            if (tid == 0) { while (g_bdone == 0) __nanosleep(100); }
            __syncthreads();
            __threadfence();
        }
    } else {
        // ============ consumer: prefetch own agent's U chunk0, then spin ============
        next_static = cta - NPROD;
        const float4* pu4s = (const float4*)pu + (size_t)next_static * 8192;
        issue_A_U(0, smem, pu4s, tid);
        CP_COMMIT();                         // group g0 (pre-spin)
        if (tid == 0) { while (g_bdone == 0) __nanosleep(100); }
        __syncthreads();
        __threadfence();
    }

    // ============ work loop ============
    for (;;) {
        int agent, base, nb;
        bool pre;
        if (next_static >= 0) {
            agent = next_static;
            next_static = -1;
            base = 0;
            nb = min(SB, g_cnt2[agent]);
            pre = true;
            if (nb <= 0) { CP_WAIT0(); __syncthreads(); continue; }  // drain prefetch
        } else {
            if (tid == 0) s_item = atomicAdd(&g_ifetch, 1);
            __syncthreads();
            const int it = s_item;
            __syncthreads();
            if (it >= g_nitems) break;
            const int info = g_items[it];
            agent = info & 255;
            base  = (info >> 8) * SB;
            nb    = min(SB, g_cnt2[agent] - base);
            pre   = false;
        }

        const float4* pu4 = (const float4*)pu + (size_t)agent * 8192;
        const float4* pv4 = (const float4*)pv + (size_t)agent * 8192;

        if (tid < SB) stoks[tid] = g_toks[agent][base + min(tid, nb - 1)];
        __syncthreads();

        const bool gvalid = (TPW * wid) < nb;
        int  gt[TPW]; bool vd[TPW]; int tk[TPW];
        #pragma unroll
        for (int i = 0; i < TPW; ++i) {
            tk[i] = min(TPW * wid + i, nb - 1);
            vd[i] = (TPW * wid + i) < nb;
            gt[i] = stoks[tk[i]];
        }

        // ---- prologue: groups g0..g3 (g0 = U0, may be pre-issued) ----
        if (!pre) { issue_A_U(0, smem, pu4, tid); CP_COMMIT(); }
        issue_A_H(0, smem, h4, stoks, tid); CP_COMMIT();
        issue_chunk(1, smem, pu4, pv4, h4, stoks, tid); CP_COMMIT();
        issue_chunk(2, smem, pu4, pv4, h4, stoks, tid); CP_COMMIT();

        // ================= phase A: chunks 0..15 =================
        u64 Ax[TPW], Az[TPW];
        #pragma unroll
        for (int i = 0; i < TPW; ++i) { Ax[i] = 0; Az[i] = 0; }

        #pragma unroll 1
        for (int t = 0; t < 16; ++t) {
            CP_WAIT2();
            __syncthreads();
            issue_chunk(t + 3, smem, pu4, pv4, h4, stoks, tid);
            CP_COMMIT();

            if (gvalid) {
                const float* ubl = smem + (t & 3) * STAGE_F + lane;
                const ulonglong2* hb = (const ulonglong2*)(smem + (t & 3) * STAGE_F + 2048);

                #pragma unroll 4
                for (int k4 = 0; k4 < 16; ++k4) {
                    const float* up = ubl + k4 * 128;
                    u64 u01 = pack2(up[0],  up[32]);
                    u64 u23 = pack2(up[64], up[96]);
                    #pragma unroll
                    for (int i = 0; i < TPW; ++i) {
                        ulonglong2 x = hb[tk[i] * 16 + k4];
                        Ax[i] = fma2(x.x, u01, Ax[i]);
                        Az[i] = fma2(x.y, u23, Az[i]);
                    }
                }
            }
        }

        // pack (iv,iv) into binter (per-warp private rows)
        if (gvalid) {
            #pragma unroll
            for (int i = 0; i < TPW; ++i) {
                float f0, f1, f2, f3;
                unpack2(Ax[i], f0, f1);
                unpack2(Az[i], f2, f3);
                const float iv = (f0 + f1) + (f2 + f3);
                bint[tk[i] * 32 + lane] = pack2(iv, iv);
            }
        }
        __syncwarp();

        // ================= phase B: chunks 16..23 =================
        u64 S[TPW], Q[TPW];
        #pragma unroll
        for (int i = 0; i < TPW; ++i) { S[i] = 0; Q[i] = 0; }

        #pragma unroll 1
        for (int j = 0; j < 8; ++j) {
            const int t = 16 + j;
            if (j < 6)       { CP_WAIT2(); }
            else if (j == 6) { CP_WAIT1(); }
            else             { CP_WAIT0(); }
            __syncthreads();
            if (t + 3 < 24) {
                issue_chunk(t + 3, smem, pu4, pv4, h4, stoks, tid);
                CP_COMMIT();
            }

            if (gvalid) {
                const ulonglong2* vb = (const ulonglong2*)(smem + (t & 3) * STAGE_F);

                u64 Px[TPW], Pz[TPW];
                #pragma unroll
                for (int i = 0; i < TPW; ++i) { Px[i] = 0; Pz[i] = 0; }

                #pragma unroll 4
                for (int rb = 0; rb < 16; ++rb) {
                    ulonglong2 v0 = vb[(2 * rb)     * 32 + lane];
                    ulonglong2 v1 = vb[(2 * rb + 1) * 32 + lane];
                    #pragma unroll
                    for (int i = 0; i < TPW; ++i) {
                        ulonglong2 bb = ((const ulonglong2*)(bint + tk[i] * 32))[rb];
                        Px[i] = fma2(bb.x, v0.x, Px[i]);
                        Pz[i] = fma2(bb.x, v0.y, Pz[i]);
                        Px[i] = fma2(bb.y, v1.x, Px[i]);
                        Pz[i] = fma2(bb.y, v1.y, Pz[i]);
                    }
                }

                #pragma unroll
                for (int i = 0; i < TPW; ++i) {
                    if (!vd[i]) continue;
                    ulonglong2 hv = h2[(size_t)gt[i] * 256 + j * 32 + lane];
                    u64 dx = fma2(al2, Px[i], hv.x);
                    u64 dz = fma2(al2, Pz[i], hv.y);
                    S[i] = add2(S[i], add2(dx, dz));
                    Q[i] = fma2(dx, dx, Q[i]);
                    Q[i] = fma2(dz, dz, Q[i]);
                    ulonglong2 dd; dd.x = dx; dd.y = dz;
                    out2[(size_t)gt[i] * 256 + j * 32 + lane] = dd;
                }
            }
        }

        // ---- LN finalize + normalize ----
        if (gvalid) {
            float s[TPW], q[TPW];
            #pragma unroll
            for (int i = 0; i < TPW; ++i) {
                float lo, hi;
                unpack2(S[i], lo, hi); s[i] = lo + hi;
                unpack2(Q[i], lo, hi); q[i] = lo + hi;
            }
            #pragma unroll
            for (int o = 16; o > 0; o >>= 1) {
                #pragma unroll
                for (int i = 0; i < TPW; ++i) {
                    s[i] += __shfl_xor_sync(0xffffffffu, s[i], o);
                    q[i] += __shfl_xor_sync(0xffffffffu, q[i], o);
                }
            }
            const ulonglong2* g2 = (const ulonglong2*)gamma;
            const ulonglong2* b2 = (const ulonglong2*)beta;
            #pragma unroll
            for (int i = 0; i < TPW; ++i) {
                if (!vd[i]) continue;
                const float mn = s[i] * (1.0f / H_DIM);
                const float rs = rsqrtf(q[i] * (1.0f / H_DIM) - mn * mn + LN_EPS);
                const u64 nm2 = pack2(-mn, -mn);
                const u64 rs2 = pack2(rs, rs);
                ulonglong2* op = out2 + (size_t)gt[i] * 256 + lane;
                #pragma unroll
                for (int c = 0; c < 8; ++c) {
                    ulonglong2 d = op[c * 32];
                    ulonglong2 g = g2[c * 32 + lane];
                    ulonglong2 bb = b2[c * 32 + lane];
                    u64 tx = mul2(add2(d.x, nm2), rs2);
                    u64 tz = mul2(add2(d.y, nm2), rs2);
                    ulonglong2 o_;
                    o_.x = fma2(tx, g.x, bb.x);
                    o_.y = fma2(tz, g.y, bb.y);
                    op[c * 32] = o_;
                }
            }
        }
        __syncthreads();   // ring/stoks/s_item reuse safety
    }

    // ---- reset flags for next replay (last CTA to finish) ----
    if (tid == 0) {
        int f = atomicAdd(&g_fin, 1);
        if (f == GRID_MAIN - 1) {
            g_sdone = 0;
            g_bdone = 0;
            g_fin   = 0;
        }
    }
}

extern "C" void kernel_launch(void* const* d_in, const int* in_sizes, int n_in,
                              void* d_out, int out_size)
{
    const float* h     = (const float*)d_in[0];
    const float* la    = (const float*)d_in[1];
    const float* gamma = (const float*)d_in[2];
    const float* beta  = (const float*)d_in[3];
    const float* pu    = (const float*)d_in[4];
    const float* pv    = (const float*)d_in[5];
    const int*   ids   = (const int*)d_in[6];
    float*       out   = (float*)d_out;

    cudaFuncSetAttribute(div_inject_kernel,
                         cudaFuncAttributeMaxDynamicSharedMemorySize, SMEM_BYTES);
    div_inject_kernel<<<GRID_MAIN, NTH, SMEM_BYTES>>>(h, la, gamma, beta, pu, pv, ids, out);
}

// round 16
// speedup vs baseline: 1.0890x; 1.0890x over previous
#include <cuda_runtime.h>
#include <math.h>

#define H_DIM 1024
#define NAG 256
#define BTOK 8192
#define NTH 256
#define SB 48
#define TPW 6
#define LN_EPS 1e-5f
#define ALPHA_MAX 5.0f

typedef unsigned long long u64;

// ---- f32x2 packed math ----
__device__ __forceinline__ u64 fma2(u64 a, u64 b, u64 c) {
    u64 d;
    asm("fma.rn.f32x2 %0, %1, %2, %3;" : "=l"(d) : "l"(a), "l"(b), "l"(c));
    return d;
}
__device__ __forceinline__ u64 add2(u64 a, u64 b) {
    u64 d;
    asm("add.rn.f32x2 %0, %1, %2;" : "=l"(d) : "l"(a), "l"(b));
    return d;
}
__device__ __forceinline__ u64 mul2(u64 a, u64 b) {
    u64 d;
    asm("mul.rn.f32x2 %0, %1, %2;" : "=l"(d) : "l"(a), "l"(b));
    return d;
}
__device__ __forceinline__ u64 pack2(float lo, float hi) {
    u64 d;
    asm("mov.b64 %0, {%1, %2};" : "=l"(d) : "f"(lo), "f"(hi));
    return d;
}
__device__ __forceinline__ void unpack2(u64 v, float& lo, float& hi) {
    asm("mov.b64 {%0, %1}, %2;" : "=f"(lo), "=f"(hi) : "l"(v));
}

// ---- cp.async helpers ----
__device__ __forceinline__ void cp16(void* s, const void* g) {
    unsigned sa = (unsigned)__cvta_generic_to_shared(s);
    asm volatile("cp.async.cg.shared.global [%0], [%1], 16;\n" :: "r"(sa), "l"(g));
}
#define CP_COMMIT() asm volatile("cp.async.commit_group;\n" ::: "memory")
#define CP_WAIT2()  asm volatile("cp.async.wait_group 2;\n" ::: "memory")
#define CP_WAIT1()  asm volatile("cp.async.wait_group 1;\n" ::: "memory")
#define CP_WAIT0()  asm volatile("cp.async.wait_group 0;\n" ::: "memory")

// SMEM layout (floats):
//   ring     4 x 5120 @ 0       (80 KB; A-stage: U 2048 + h 3072; B-stage: V 4096)
//   binter   3072 f   @ 20480   (12 KB: 48 tok x 32 r duplicated u64 pairs)
//   stoksw   48 int   @ 23552   (current batch window)
//   stoksa   256 int  @ 23600   (all tokens of this agent, unordered)
#define STAGE_F 5120
#define OFF_BI 20480
#define OFF_TW 23552
#define OFF_TA 23600
#define SMEM_BYTES ((23600 + 256) * 4)

__device__ __forceinline__ void issue_A_U(int t, float* smem, const float4* pu4, int tid) {
    float4* dst = (float4*)(smem + (t & 3) * STAGE_F);
    cp16(dst + tid,       pu4 + t * 512 + tid);
    cp16(dst + 256 + tid, pu4 + t * 512 + 256 + tid);
}
__device__ __forceinline__ void issue_A_H(int t, float* smem, const float4* h4,
                                          const int* stoksw, int tid) {
    float4* dst = (float4*)(smem + (t & 3) * STAGE_F);
    #pragma unroll
    for (int i = 0; i < 3; ++i) {
        const int idx = tid + i * 256;
        const int tok = idx >> 4, cc = idx & 15;
        cp16(dst + 512 + idx, h4 + (size_t)stoksw[tok] * 256 + t * 16 + cc);
    }
}
__device__ __forceinline__ void issue_chunk(int t, float* smem, const float4* pu4,
                                            const float4* pv4, const float4* h4,
                                            const int* stoksw, int tid) {
    if (t < 16) {
        issue_A_U(t, smem, pu4, tid);
        issue_A_H(t, smem, h4, stoksw, tid);
    } else {
        const int j = t - 16;
        float4* dst = (float4*)(smem + (t & 3) * STAGE_F);
        #pragma unroll
        for (int i = 0; i < 4; ++i) {
            const int idx = tid + i * 256;
            const int r = idx >> 5, cc = idx & 31;
            cp16(dst + idx, pv4 + r * 256 + j * 32 + cc);
        }
    }
}

__global__ __launch_bounds__(NTH, 2)
void div_inject_kernel(const float* __restrict__ h,
                       const float* __restrict__ log_alpha,
                       const float* __restrict__ gamma,
                       const float* __restrict__ beta,
                       const float* __restrict__ pu,
                       const float* __restrict__ pv,
                       const int*   __restrict__ ids,
                       float*       __restrict__ out)
{
    extern __shared__ float smem[];
    u64* bint   = (u64*)(smem + OFF_BI);
    int* stoksw = (int*)(smem + OFF_TW);
    int* stoksa = (int*)(smem + OFF_TA);
    __shared__ int s_cnt;

    const int tid  = threadIdx.x;
    const int lane = tid & 31;
    const int wid  = tid >> 5;
    const int agent = blockIdx.x;

    const float4* pu4 = (const float4*)pu + (size_t)agent * 8192;
    const float4* pv4 = (const float4*)pv + (size_t)agent * 8192;
    const float4* h4  = (const float4*)h;
    const ulonglong2* h2 = (const ulonglong2*)h;
    ulonglong2* out2 = (ulonglong2*)out;

    // ---- prefetch U chunk 0 (group G0) BEFORE the scan ----
    issue_A_U(0, smem, pu4, tid);
    CP_COMMIT();

    // ---- self-service scan: find this agent's tokens (order irrelevant) ----
    if (tid == 0) s_cnt = 0;
    __syncthreads();
    {
        const int4* ids4 = (const int4*)ids;   // 2048 int4
        #pragma unroll
        for (int k = 0; k < 8; ++k) {
            const int i4 = tid + k * 256;
            int4 v = ids4[i4];
            const int b = i4 * 4;
            if ((v.x & (NAG - 1)) == agent) stoksa[atomicAdd(&s_cnt, 1)] = b;
            if ((v.y & (NAG - 1)) == agent) stoksa[atomicAdd(&s_cnt, 1)] = b + 1;
            if ((v.z & (NAG - 1)) == agent) stoksa[atomicAdd(&s_cnt, 1)] = b + 2;
            if ((v.w & (NAG - 1)) == agent) stoksa[atomicAdd(&s_cnt, 1)] = b + 3;
        }
    }
    __syncthreads();
    const int total = s_cnt;
    if (total == 0) { CP_WAIT0(); return; }

    const float alpha = fminf(expf(log_alpha[0]), ALPHA_MAX);
    const u64 al2 = pack2(alpha, alpha);

    bool first = true;
    for (int base = 0; base < total; base += SB) {
        const int nb = min(SB, total - base);

        if (tid < SB) stoksw[tid] = stoksa[base + min(tid, nb - 1)];
        __syncthreads();

        const bool gvalid = (TPW * wid) < nb;
        int  gt[TPW]; bool vd[TPW]; int tk[TPW];
        #pragma unroll
        for (int i = 0; i < TPW; ++i) {
            tk[i] = min(TPW * wid + i, nb - 1);
            vd[i] = (TPW * wid + i) < nb;
            gt[i] = stoksw[tk[i]];
        }

        // ---- prologue groups: G0=U0 (pre-issued on first batch), G1=h0, G2=chunk1, G3=chunk2 ----
        if (!first) { issue_A_U(0, smem, pu4, tid); CP_COMMIT(); }
        first = false;
        issue_A_H(0, smem, h4, stoksw, tid); CP_COMMIT();
        issue_chunk(1, smem, pu4, pv4, h4, stoksw, tid); CP_COMMIT();
        issue_chunk(2, smem, pu4, pv4, h4, stoksw, tid); CP_COMMIT();

        // ================= phase A: chunks 0..15 =================
        u64 Ax[TPW], Az[TPW];
        #pragma unroll
        for (int i = 0; i < TPW; ++i) { Ax[i] = 0; Az[i] = 0; }

        #pragma unroll 1
        for (int t = 0; t < 16; ++t) {
            CP_WAIT2();
            __syncthreads();
            issue_chunk(t + 3, smem, pu4, pv4, h4, stoksw, tid);
            CP_COMMIT();

            if (gvalid) {
                const float* ubl = smem + (t & 3) * STAGE_F + lane;
                const ulonglong2* hb = (const ulonglong2*)(smem + (t & 3) * STAGE_F + 2048);

                #pragma unroll 4
                for (int k4 = 0; k4 < 16; ++k4) {
                    const float* up = ubl + k4 * 128;
                    u64 u01 = pack2(up[0],  up[32]);
                    u64 u23 = pack2(up[64], up[96]);
                    #pragma unroll
                    for (int i = 0; i < TPW; ++i) {
                        ulonglong2 x = hb[tk[i] * 16 + k4];
                        Ax[i] = fma2(x.x, u01, Ax[i]);
                        Az[i] = fma2(x.y, u23, Az[i]);
                    }
                }
            }
        }

        // pack (iv,iv) into binter (per-warp private rows)
        if (gvalid) {
            #pragma unroll
            for (int i = 0; i < TPW; ++i) {
                float f0, f1, f2, f3;
                unpack2(Ax[i], f0, f1);
                unpack2(Az[i], f2, f3);
                const float iv = (f0 + f1) + (f2 + f3);
                bint[tk[i] * 32 + lane] = pack2(iv, iv);
            }
        }
        __syncwarp();

        // ================= phase B: chunks 16..23 =================
        u64 S[TPW], Q[TPW];
        #pragma unroll
        for (int i = 0; i < TPW; ++i) { S[i] = 0; Q[i] = 0; }

        #pragma unroll 1
        for (int j = 0; j < 8; ++j) {
            const int t = 16 + j;
            if (j < 6)       { CP_WAIT2(); }
            else if (j == 6) { CP_WAIT1(); }
            else             { CP_WAIT0(); }
            __syncthreads();
            if (t + 3 < 24) {
                issue_chunk(t + 3, smem, pu4, pv4, h4, stoksw, tid);
                CP_COMMIT();
            }

            if (gvalid) {
                const ulonglong2* vb = (const ulonglong2*)(smem + (t & 3) * STAGE_F);

                u64 Px[TPW], Pz[TPW];
                #pragma unroll
                for (int i = 0; i < TPW; ++i) { Px[i] = 0; Pz[i] = 0; }

                #pragma unroll 4
                for (int rb = 0; rb < 16; ++rb) {
                    ulonglong2 v0 = vb[(2 * rb)     * 32 + lane];
                    ulonglong2 v1 = vb[(2 * rb + 1) * 32 + lane];
                    #pragma unroll
                    for (int i = 0; i < TPW; ++i) {
                        ulonglong2 bb = ((const ulonglong2*)(bint + tk[i] * 32))[rb];
                        Px[i] = fma2(bb.x, v0.x, Px[i]);
                        Pz[i] = fma2(bb.x, v0.y, Pz[i]);
                        Px[i] = fma2(bb.y, v1.x, Px[i]);
                        Pz[i] = fma2(bb.y, v1.y, Pz[i]);
                    }
                }

                #pragma unroll
                for (int i = 0; i < TPW; ++i) {
                    if (!vd[i]) continue;
                    ulonglong2 hv = h2[(size_t)gt[i] * 256 + j * 32 + lane];
                    u64 dx = fma2(al2, Px[i], hv.x);
                    u64 dz = fma2(al2, Pz[i], hv.y);
                    S[i] = add2(S[i], add2(dx, dz));
                    Q[i] = fma2(dx, dx, Q[i]);
                    Q[i] = fma2(dz, dz, Q[i]);
                    ulonglong2 dd; dd.x = dx; dd.y = dz;
                    out2[(size_t)gt[i] * 256 + j * 32 + lane] = dd;
                }
            }
        }

        // ---- LN finalize + normalize ----
        if (gvalid) {
            float s[TPW], q[TPW];
            #pragma unroll
            for (int i = 0; i < TPW; ++i) {
                float lo, hi;
                unpack2(S[i], lo, hi); s[i] = lo + hi;
                unpack2(Q[i], lo, hi); q[i] = lo + hi;
            }
            #pragma unroll
            for (int o = 16; o > 0; o >>= 1) {
                #pragma unroll
                for (int i = 0; i < TPW; ++i) {
                    s[i] += __shfl_xor_sync(0xffffffffu, s[i], o);
                    q[i] += __shfl_xor_sync(0xffffffffu, q[i], o);
                }
            }
            const ulonglong2* g2 = (const ulonglong2*)gamma;
            const ulonglong2* b2 = (const ulonglong2*)beta;
            #pragma unroll
            for (int i = 0; i < TPW; ++i) {
                if (!vd[i]) continue;
                const float mn = s[i] * (1.0f / H_DIM);
                const float rs = rsqrtf(q[i] * (1.0f / H_DIM) - mn * mn + LN_EPS);
                const u64 nm2 = pack2(-mn, -mn);
                const u64 rs2 = pack2(rs, rs);
                ulonglong2* op = out2 + (size_t)gt[i] * 256 + lane;
                #pragma unroll
                for (int c = 0; c < 8; ++c) {
                    ulonglong2 d = op[c * 32];
                    ulonglong2 g = g2[c * 32 + lane];
                    ulonglong2 bb = b2[c * 32 + lane];
                    u64 tx = mul2(add2(d.x, nm2), rs2);
                    u64 tz = mul2(add2(d.y, nm2), rs2);
                    ulonglong2 o_;
                    o_.x = fma2(tx, g.x, bb.x);
                    o_.y = fma2(tz, g.y, bb.y);
                    op[c * 32] = o_;
                }
            }
        }
        __syncthreads();   // ring/stoksw reuse safety for next batch
    }
}

extern "C" void kernel_launch(void* const* d_in, const int* in_sizes, int n_in,
                              void* d_out, int out_size)
{
    const float* h     = (const float*)d_in[0];
    const float* la    = (const float*)d_in[1];
    const float* gamma = (const float*)d_in[2];
    const float* beta  = (const float*)d_in[3];
    const float* pu    = (const float*)d_in[4];
    const float* pv    = (const float*)d_in[5];
    const int*   ids   = (const int*)d_in[6];
    float*       out   = (float*)d_out;

    cudaFuncSetAttribute(div_inject_kernel,
                         cudaFuncAttributeMaxDynamicSharedMemorySize, SMEM_BYTES);
    div_inject_kernel<<<NAG, NTH, SMEM_BYTES>>>(h, la, gamma, beta, pu, pv, ids, out);
}